// round 3
// baseline (speedup 1.0000x reference)
#include <cuda_runtime.h>

#define R_BINS 64
#define Z_BINS 64
#define NBINS  (R_BINS * Z_BINS)

__device__ __constant__ float kDR    = 10.0f / 64.0f;   // 0.15625 (exact)
__device__ __constant__ float kZMIN  = -2.0f;
__device__ __constant__ float kINVDZ = 16.0f;           // 1/DZ, exact
#define PI_F 3.14159265358979f

__global__ void zero_out_kernel(float* __restrict__ out) {
    int i = blockIdx.x * blockDim.x + threadIdx.x;
    if (i < NBINS) out[i] = 0.0f;
}

__device__ __forceinline__ void accum_point(float x, float y, float z, float m,
                                            float* __restrict__ sh) {
    float r = sqrtf(fmaf(x, x, y * y));
    // r >= 0 always; match reference floor((r - R_MIN)/DR) with true division
    int bi = (int)(r / kDR);                       // trunc == floor for r>=0
    float fj = floorf((z - kZMIN) * kINVDZ);       // 1/DZ exact -> mul ok
    int bj = (int)fj;
    if (bi < R_BINS && bj >= 0 && bj < Z_BINS) {
        atomicAdd(&sh[bi * Z_BINS + bj], m);
    }
}

__global__ void __launch_bounds__(256)
hist_kernel(const float4* __restrict__ pos4,   // 3 float4 per 4 points
            const float4* __restrict__ mass4,  // 1 float4 per 4 points
            float* __restrict__ out,
            int n4)                            // N/4
{
    __shared__ float sh[NBINS];
    for (int i = threadIdx.x; i < NBINS; i += blockDim.x) sh[i] = 0.0f;
    __syncthreads();

    int stride = gridDim.x * blockDim.x;
    for (int t = blockIdx.x * blockDim.x + threadIdx.x; t < n4; t += stride) {
        float4 a = pos4[3 * t + 0];
        float4 b = pos4[3 * t + 1];
        float4 c = pos4[3 * t + 2];
        float4 m = mass4[t];
        accum_point(a.x, a.y, a.z, m.x, sh);
        accum_point(a.w, b.x, b.y, m.y, sh);
        accum_point(b.z, b.w, c.x, m.z, sh);
        accum_point(c.y, c.z, c.w, m.w, sh);
    }
    __syncthreads();

    for (int i = threadIdx.x; i < NBINS; i += blockDim.x) {
        float v = sh[i];
        if (v != 0.0f) atomicAdd(&out[i], v);
    }
}

__global__ void normalize_kernel(float* __restrict__ out) {
    int idx = blockIdx.x * blockDim.x + threadIdx.x;
    if (idx < NBINS) {
        int i = idx >> 6;  // r bin
        // Match reference: redge[k] = k*DR in fp32; area = pi*(r1^2 - r0^2); vol = area*DZ
        float r0 = (float)i * kDR;
        float r1 = (float)(i + 1) * kDR;
        float area = PI_F * (r1 * r1 - r0 * r0);
        float vol = area * (4.0f / 64.0f);  // DZ = 0.0625 exact
        out[idx] = out[idx] / vol;
    }
}

extern "C" void kernel_launch(void* const* d_in, const int* in_sizes, int n_in,
                              void* d_out, int out_size) {
    const float4* pos4  = (const float4*)d_in[0];  // positions: (N,3) f32
    const float4* mass4 = (const float4*)d_in[1];  // masses: (N,) f32
    float* out = (float*)d_out;

    int n  = in_sizes[1];        // N (element count of masses)
    int n4 = n >> 2;             // N divisible by 4 (N = 2^24)

    zero_out_kernel<<<(NBINS + 255) / 256, 256>>>(out);

    const int threads = 256;
    const int blocks  = 148 * 4;  // persistent-ish grid, 4 waves of occupancy
    hist_kernel<<<blocks, threads>>>(pos4, mass4, out, n4);

    normalize_kernel<<<(NBINS + 255) / 256, 256>>>(out);
}

// round 7
// speedup vs baseline: 1.0248x; 1.0248x over previous
#include <cuda_runtime.h>

#define R_BINS 64
#define Z_BINS 64
#define NBINS  (R_BINS * Z_BINS)
#define HSTRIDE 65                       // pad: bank = (bi + bj) % 32
#define GRID_CTAS (148 * 4)              // all co-resident at 4 CTAs/SM
#define NTHREADS 256

#define PI_F     3.14159265358979f
#define INV_DR   6.4f                    // 1/0.15625
#define DR_F     0.15625f
#define DZ_F     0.0625f

__device__ unsigned int g_c1 = 0;        // zeroing-done arrivals (reaches 16)
__device__ unsigned int g_c2 = 0;        // flush-done arrivals (reaches grid)

__device__ __forceinline__ void accum_point(float x, float y, float z, float m,
                                            float* __restrict__ h) {
    float r  = sqrtf(fmaf(x, x, y * y));
    int   bi = (int)(r * INV_DR);                 // r >= 0 -> trunc == floor
    float fj = floorf((z + 2.0f) * 16.0f);        // matches ref: (z - zmin) * (1/DZ), both exact-ish
    int   bj = (int)fj;
    if (bi < R_BINS && (unsigned)bj < Z_BINS) {
        atomicAdd(&h[bi * HSTRIDE + bj], m);
    }
}

__global__ void __launch_bounds__(NTHREADS)
fused_hist_kernel(const float4* __restrict__ pos4,   // (N,3) f32 -> 6 float4 per 8 pts
                  const float4* __restrict__ mass4,  // (N,)  f32 -> 2 float4 per 8 pts
                  float* __restrict__ out,
                  int n8)                            // N/8
{
    __shared__ float sh[2][R_BINS * HSTRIDE];

    const int tid = threadIdx.x;
    const int wid = tid >> 5;

    // ---- Phase 0: CTAs 0..15 zero d_out (poisoned by harness; re-zeroed every replay)
    if (blockIdx.x < 16) {
        out[blockIdx.x * NTHREADS + tid] = 0.0f;
        __threadfence();
        __syncthreads();
        if (tid == 0) atomicAdd(&g_c1, 1u);
    }

    // ---- Phase 1: private histogram
    float* hist = sh[wid & 1];
    for (int i = tid; i < 2 * R_BINS * HSTRIDE; i += NTHREADS)
        (&sh[0][0])[i] = 0.0f;
    __syncthreads();

    const int stride = gridDim.x * NTHREADS;
    for (int t = blockIdx.x * NTHREADS + tid; t < n8; t += stride) {
        // 8 points: 6 float4 of positions, 2 float4 of masses (front-batched, MLP=8)
        const float4* p = pos4 + 6 * (size_t)t;
        float4 p0 = p[0], p1 = p[1], p2 = p[2], p3 = p[3], p4 = p[4], p5 = p[5];
        float4 m0 = mass4[2 * t + 0];
        float4 m1 = mass4[2 * t + 1];

        accum_point(p0.x, p0.y, p0.z, m0.x, hist);
        accum_point(p0.w, p1.x, p1.y, m0.y, hist);
        accum_point(p1.z, p1.w, p2.x, m0.z, hist);
        accum_point(p2.y, p2.z, p2.w, m0.w, hist);
        accum_point(p3.x, p3.y, p3.z, m1.x, hist);
        accum_point(p3.w, p4.x, p4.y, m1.y, hist);
        accum_point(p4.z, p4.w, p5.x, m1.z, hist);
        accum_point(p5.y, p5.z, p5.w, m1.w, hist);
    }
    __syncthreads();

    // ---- Phase 2: wait until d_out is zeroed (CTAs 0..15 are first-wave residents)
    if (tid == 0) {
        while (atomicAdd(&g_c1, 0u) < 16u) { __nanosleep(64); }
    }
    __syncthreads();
    __threadfence();

    // ---- Phase 3: flush, pre-scaled by 1/volume (folds the normalize kernel in)
    for (int i = tid; i < NBINS; i += NTHREADS) {
        int row = i >> 6;
        int col = i & 63;
        float v = sh[0][row * HSTRIDE + col] + sh[1][row * HSTRIDE + col];
        if (v != 0.0f) {
            float r0   = (float)row * DR_F;
            float r1   = (float)(row + 1) * DR_F;
            float vol  = PI_F * (r1 * r1 - r0 * r0) * DZ_F;
            atomicAdd(&out[i], v / vol);
        }
    }

    // ---- Phase 4: last CTA resets counters (deterministic across graph replays)
    __threadfence();
    __syncthreads();
    if (tid == 0) {
        unsigned int v = atomicAdd(&g_c2, 1u);
        if (v == gridDim.x - 1) {
            atomicExch(&g_c1, 0u);
            atomicExch(&g_c2, 0u);
        }
    }
}

extern "C" void kernel_launch(void* const* d_in, const int* in_sizes, int n_in,
                              void* d_out, int out_size) {
    const float4* pos4  = (const float4*)d_in[0];   // positions (N,3) f32
    const float4* mass4 = (const float4*)d_in[1];   // masses (N,) f32
    float* out = (float*)d_out;

    int n  = in_sizes[1];     // N = 2^24
    int n8 = n >> 3;

    fused_hist_kernel<<<GRID_CTAS, NTHREADS>>>(pos4, mass4, out, n8);
}